// round 3
// baseline (speedup 1.0000x reference)
#include <cuda_runtime.h>

#define NN 256
#define BB 2
#define NNODE (BB*NN)

#define RSQRT3 0.5773502691896258f
#define INV_FAN 0.1767766952966369f   // 1/sqrt(32)

// scratch: G[node][f*4+c], f in [0,33) where f==32 is the bias (constant-1) feature
__device__ float g_G[NNODE][33*4];

#define PACK_F32X2(out, lo, hi) \
    asm("mov.b64 %0, {%1, %2};" : "=l"(out) : "f"(lo), "f"(hi))
#define UNPACK_F32X2(lo, hi, in) \
    asm("mov.b64 {%0, %1}, %2;" : "=f"(lo), "=f"(hi) : "l"(in))
#define FMA_F32X2(d, a, b, c) \
    asm("fma.rn.f32x2 %0, %1, %2, %3;" : "=l"(d) : "l"(a), "l"(b), "l"(c))
#define ADD_F32X2(d, a, b) \
    asm("add.rn.f32x2 %0, %1, %2;" : "=l"(d) : "l"(a), "l"(b))

#define CP_ASYNC16(dst_u32, src_ptr) \
    asm volatile("cp.async.ca.shared.global [%0], [%1], 16;" :: "r"(dst_u32), "l"(src_ptr))
#define CP_COMMIT() asm volatile("cp.async.commit_group;" ::: "memory")
#define CP_WAIT1()  asm volatile("cp.async.wait_group 1;" ::: "memory")
#define CP_WAIT0()  asm volatile("cp.async.wait_group 0;" ::: "memory")

// ---------------------------------------------------------------------------
// Kernel A: per-(b,n) edge reduction.
// h[m,f] = relu(edge_attr[m,:] @ fc_w1[:,f] + fc_b1[f])
// G[f,c] = sum_m h[m,f] * sh'[m,c]   where sh' = edge_sh * mask * (m != n)
// G[32,c] = sum_m sh'[m,c]           (bias feature)
// ---------------------------------------------------------------------------
__global__ __launch_bounds__(256) void edge_kernel(
    const float* __restrict__ edge_attr,
    const float* __restrict__ edge_sh,
    const float* __restrict__ mask,
    const float* __restrict__ fc_w1,
    const float* __restrict__ fc_b1)
{
    __shared__ __align__(16) float ea[NN * 32];   // [m][j]  32 KB
    __shared__ __align__(16) float sh[NN * 4];    // [m][c] premultiplied
    __shared__ float w1s[32 * 32];                // [j][f]
    __shared__ float b1s[32];
    __shared__ float Gp[8][132];

    const int node = blockIdx.x;
    const int b = node >> 8;
    const int n = node & 255;
    const int t = threadIdx.x;

    const float4* ea_g = (const float4*)(edge_attr + (size_t)node * NN * 32);
    const float4* sh_g = (const float4*)(edge_sh + (size_t)node * NN * 4);
    float4* ea4 = (float4*)ea;
    float4* sh4 = (float4*)sh;

    #pragma unroll
    for (int i = t; i < NN * 8; i += 256) ea4[i] = ea_g[i];
    for (int i = t; i < 32 * 32; i += 256) w1s[i] = fc_w1[i];
    if (t < 32) b1s[t] = fc_b1[t];
    {
        // stage sh premultiplied by mask * (m != n); own-write-own-read, no sync
        float mf = mask[b * NN + t] * (t != n ? 1.0f : 0.0f);
        float4 s = sh_g[t];
        s.x *= mf; s.y *= mf; s.z *= mf; s.w *= mf;
        sh4[t] = s;
    }
    __syncthreads();

    const int f  = t & 31;   // lane = feature column
    const int mg = t >> 5;   // warp = m-group

    // pack this thread's W1 column into f32x2 registers
    unsigned long long w1p[16];
    #pragma unroll
    for (int j = 0; j < 16; j++)
        PACK_F32X2(w1p[j], w1s[(2*j) * 32 + f], w1s[(2*j+1) * 32 + f]);
    const float bias1 = b1s[f];

    unsigned long long acc01 = 0ULL, acc23 = 0ULL;
    const ulonglong2* sh2 = (const ulonglong2*)sh;

    #pragma unroll 2
    for (int m = mg; m < NN; m += 16) {
        const ulonglong2* rA = (const ulonglong2*)(ea + m * 32);
        const ulonglong2* rB = (const ulonglong2*)(ea + (m + 8) * 32);
        unsigned long long cA0 = 0ULL, cA1 = 0ULL, cA2 = 0ULL, cA3 = 0ULL;
        unsigned long long cB0 = 0ULL, cB1 = 0ULL, cB2 = 0ULL, cB3 = 0ULL;
        #pragma unroll
        for (int k = 0; k < 4; k++) {
            ulonglong2 ua = rA[2*k];
            ulonglong2 ua2 = rA[2*k + 1];
            ulonglong2 ub = rB[2*k];
            ulonglong2 ub2 = rB[2*k + 1];
            FMA_F32X2(cA0, ua.x,  w1p[4*k+0], cA0);
            FMA_F32X2(cA1, ua.y,  w1p[4*k+1], cA1);
            FMA_F32X2(cA2, ua2.x, w1p[4*k+2], cA2);
            FMA_F32X2(cA3, ua2.y, w1p[4*k+3], cA3);
            FMA_F32X2(cB0, ub.x,  w1p[4*k+0], cB0);
            FMA_F32X2(cB1, ub.y,  w1p[4*k+1], cB1);
            FMA_F32X2(cB2, ub2.x, w1p[4*k+2], cB2);
            FMA_F32X2(cB3, ub2.y, w1p[4*k+3], cB3);
        }
        ADD_F32X2(cA0, cA0, cA1);
        ADD_F32X2(cA2, cA2, cA3);
        ADD_F32X2(cA0, cA0, cA2);
        ADD_F32X2(cB0, cB0, cB1);
        ADD_F32X2(cB2, cB2, cB3);
        ADD_F32X2(cB0, cB0, cB2);
        float a_lo, a_hi, b_lo, b_hi;
        UNPACK_F32X2(a_lo, a_hi, cA0);
        UNPACK_F32X2(b_lo, b_hi, cB0);
        float h0 = fmaxf(a_lo + a_hi + bias1, 0.0f);
        float h1 = fmaxf(b_lo + b_hi + bias1, 0.0f);
        unsigned long long h02, h12;
        PACK_F32X2(h02, h0, h0);
        PACK_F32X2(h12, h1, h1);
        ulonglong2 sa = sh2[m];
        ulonglong2 sb = sh2[m + 8];
        FMA_F32X2(acc01, h02, sa.x, acc01);
        FMA_F32X2(acc23, h02, sa.y, acc23);
        FMA_F32X2(acc01, h12, sb.x, acc01);
        FMA_F32X2(acc23, h12, sb.y, acc23);
    }

    float o0, o1, o2, o3;
    UNPACK_F32X2(o0, o1, acc01);
    UNPACK_F32X2(o2, o3, acc23);
    Gp[mg][f*4+0] = o0;
    Gp[mg][f*4+1] = o1;
    Gp[mg][f*4+2] = o2;
    Gp[mg][f*4+3] = o3;

    // bias feature: G[32][c] = sum_m sh'[m][c]
    if (t < 32) {
        int c = t & 3, mq = t >> 2;
        float s = 0.f;
        #pragma unroll 8
        for (int m = mq; m < NN; m += 8) s += sh[m * 4 + c];
        Gp[mq][128 + c] = s;
    }
    __syncthreads();

    if (t < 132) {
        float s = 0.f;
        #pragma unroll
        for (int g = 0; g < 8; g++) s += Gp[g][t];
        g_G[node][t] = s;
    }
}

// ---------------------------------------------------------------------------
// Kernel B: per-node epilogue, 4 nodes/block, 128 blocks.
// W2' = [fc_w2; fc_b2] (33 x 1024) streamed through smem via cp.async,
// each element contributing directly to out_s / out_v with per-node
// coefficients. Then scale, output linear (/4), residual.
// ---------------------------------------------------------------------------

// dynamic smem layout (floats)
#define OFF_STAGE   0                          // [2][4096]
#define OFF_PARTS   (OFF_STAGE + 2*4096)       // [4][16][68]
#define OFF_PARTV   (OFF_PARTS + 4*16*68)      // [4][48][68]
#define OFF_GS      (OFF_PARTV + 4*48*68)      // [4][132]
#define OFF_SIN     (OFF_GS + 4*132)           // [4][16]
#define OFF_VIN     (OFF_SIN + 64)             // [4][48]
#define OFF_WLS     (OFF_VIN + 192)            // 256
#define OFF_WLV     (OFF_WLS + 256)
#define OFF_WOS     (OFF_WLV + 256)
#define OFF_WOV     (OFF_WOS + 256)
#define OFF_OUTS    (OFF_WOV + 256)            // [4][16]
#define OFF_OUTV    (OFF_OUTS + 64)            // [4][48]
#define OFF_RED     (OFF_OUTV + 192)           // [8]
#define OFF_DSUM    (OFF_RED + 8)              // [1]
#define SMEM_FLOATS (OFF_DSUM + 1)
#define SMEM_BYTES  (SMEM_FLOATS * 4)

__device__ __forceinline__ void chunk_compute(
    const float4* __restrict__ S, int fbase, int nrows,
    const float* __restrict__ Gs,
    const float* si, const float* x0a, const float* x1a, const float* x2a,
    float accS[4][4], float accV[4][12], int oq, int g)
{
    int f_local = g >> 4;
    int i = g & 15;
    if (f_local >= nrows) return;
    int base = f_local * 256 + i * 4 + oq;
    float4 wss = S[base];
    float4 wvv = S[base + 64];
    float4 wsv = S[base + 128];
    float4 wvs = S[base + 192];
    int fg = fbase + f_local;
    #pragma unroll
    for (int nl = 0; nl < 4; nl++) {
        const float* Gn = Gs + nl * 132 + fg * 4;
        float g0 = Gn[0], g1 = Gn[1], g2 = Gn[2], g3 = Gn[3];
        float s  = si[nl];
        float x0 = x0a[nl], x1 = x1a[nl], x2 = x2a[nl];
        float a  = g0 * s;
        float bc = (g1 * x0 + g2 * x1 + g3 * x2) * RSQRT3;
        accS[nl][0] += a * wss.x + bc * wvv.x;
        accS[nl][1] += a * wss.y + bc * wvv.y;
        accS[nl][2] += a * wss.z + bc * wvv.z;
        accS[nl][3] += a * wss.w + bc * wvv.w;
        float c0 = g1 * s, c1 = g2 * s, c2 = g3 * s;
        float d0 = g0 * x0, d1 = g0 * x1, d2 = g0 * x2;
        accV[nl][0]  += c0 * wsv.x + d0 * wvs.x;
        accV[nl][1]  += c0 * wsv.y + d0 * wvs.y;
        accV[nl][2]  += c0 * wsv.z + d0 * wvs.z;
        accV[nl][3]  += c0 * wsv.w + d0 * wvs.w;
        accV[nl][4]  += c1 * wsv.x + d1 * wvs.x;
        accV[nl][5]  += c1 * wsv.y + d1 * wvs.y;
        accV[nl][6]  += c1 * wsv.z + d1 * wvs.z;
        accV[nl][7]  += c1 * wsv.w + d1 * wvs.w;
        accV[nl][8]  += c2 * wsv.x + d2 * wvs.x;
        accV[nl][9]  += c2 * wsv.y + d2 * wvs.y;
        accV[nl][10] += c2 * wsv.z + d2 * wvs.z;
        accV[nl][11] += c2 * wsv.w + d2 * wvs.w;
    }
}

__global__ __launch_bounds__(256) void node_kernel(
    const float* __restrict__ node_attr,
    const float* __restrict__ mask,
    const float* __restrict__ w_lin_in_s,
    const float* __restrict__ w_lin_in_v,
    const float* __restrict__ fc_w2,
    const float* __restrict__ fc_b2,
    const float* __restrict__ w_lin_out_s,
    const float* __restrict__ w_lin_out_v,
    float* __restrict__ out)
{
    extern __shared__ __align__(16) float sm[];
    float* stage = sm + OFF_STAGE;
    float* partS = sm + OFF_PARTS;
    float* partV = sm + OFF_PARTV;
    float* Gs    = sm + OFF_GS;
    float* sinS  = sm + OFF_SIN;
    float* vinS  = sm + OFF_VIN;
    float* wls   = sm + OFF_WLS;
    float* wlv   = sm + OFF_WLV;
    float* wos   = sm + OFF_WOS;
    float* wov   = sm + OFF_WOV;
    float* outsS = sm + OFF_OUTS;
    float* outvS = sm + OFF_OUTV;
    float* red   = sm + OFF_RED;

    const int t = threadIdx.x;
    const int node0 = blockIdx.x * 4;
    const int b = node0 >> 8;

    const unsigned stage_u32 = (unsigned)__cvta_generic_to_shared(stage);

    // --- prefetch W2 chunks 0 and 1 immediately (overlaps prologue) ---
    {
        unsigned d0 = stage_u32 + (unsigned)t * 16u;
        const float* s0 = fc_w2 + t * 4;
        #pragma unroll
        for (int r = 0; r < 4; r++)
            CP_ASYNC16(d0 + r * 4096u, s0 + r * 1024);
        CP_COMMIT();
        unsigned d1 = stage_u32 + 16384u + (unsigned)t * 16u;
        const float* s1 = fc_w2 + 4096 + t * 4;
        #pragma unroll
        for (int r = 0; r < 4; r++)
            CP_ASYNC16(d1 + r * 4096u, s1 + r * 1024);
        CP_COMMIT();
    }

    // --- phase 0: stage weights, G, mask reduce ---
    wls[t] = w_lin_in_s[t];
    wlv[t] = w_lin_in_v[t];
    wos[t] = w_lin_out_s[t];
    wov[t] = w_lin_out_v[t];
    if (t < 132) {
        #pragma unroll
        for (int nl = 0; nl < 4; nl++) Gs[nl*132 + t] = g_G[node0 + nl][t];
    }
    {
        float mv = mask[b * NN + t];
        #pragma unroll
        for (int o = 16; o; o >>= 1) mv += __shfl_xor_sync(0xFFFFFFFFu, mv, o);
        if ((t & 31) == 0) red[t >> 5] = mv;
    }
    __syncthreads();
    if (t == 0) {
        float s = 0.f;
        #pragma unroll
        for (int i = 0; i < 8; i++) s += red[i];
        sm[OFF_DSUM] = s - 1.0f;
    }

    // --- phase 1: s_in / v_in ---
    {
        int nl = t >> 6, u = t & 63;
        const float* na = node_attr + (size_t)(node0 + nl) * 64;
        if (u < 16) {
            float s = 0.f;
            #pragma unroll
            for (int i = 0; i < 16; i++) s += na[i] * wls[i * 16 + u];
            sinS[nl*16 + u] = s * 0.25f;
        } else {
            int idx = u - 16;
            int o = idx / 3, x = idx % 3;
            float s = 0.f;
            #pragma unroll
            for (int i = 0; i < 16; i++) s += na[16 + i * 3 + x] * wlv[i * 16 + o];
            vinS[nl*48 + o * 3 + x] = s * 0.25f;
        }
    }
    __syncthreads();

    // --- phase 2: stream W2' in 9 chunks (8 x 4 rows of fc_w2, then fc_b2) ---
    const int oq = t & 3;
    const int g  = t >> 2;

    float si[4], x0a[4], x1a[4], x2a[4];
    {
        int i = g & 15;
        #pragma unroll
        for (int nl = 0; nl < 4; nl++) {
            si[nl]  = sinS[nl*16 + i];
            x0a[nl] = vinS[nl*48 + i*3 + 0];
            x1a[nl] = vinS[nl*48 + i*3 + 1];
            x2a[nl] = vinS[nl*48 + i*3 + 2];
        }
    }

    float accS[4][4];
    float accV[4][12];
    #pragma unroll
    for (int nl = 0; nl < 4; nl++) {
        #pragma unroll
        for (int q = 0; q < 4; q++) accS[nl][q] = 0.f;
        #pragma unroll
        for (int q = 0; q < 12; q++) accV[nl][q] = 0.f;
    }

    #pragma unroll
    for (int c = 0; c < 9; c++) {
        if (c < 8) { CP_WAIT1(); } else { CP_WAIT0(); }
        __syncthreads();
        const float4* S = (const float4*)(stage + (c & 1) * 4096);
        if (c < 8)
            chunk_compute(S, c * 4, 4, Gs, si, x0a, x1a, x2a, accS, accV, oq, g);
        else
            chunk_compute(S, 32, 1, Gs, si, x0a, x1a, x2a, accS, accV, oq, g);
        __syncthreads();
        if (c + 2 <= 8) {
            int nc = c + 2;
            unsigned dst = stage_u32 + (unsigned)(nc & 1) * 16384u + (unsigned)t * 16u;
            if (nc < 8) {
                const float* src = fc_w2 + nc * 4096 + t * 4;
                #pragma unroll
                for (int r = 0; r < 4; r++)
                    CP_ASYNC16(dst + r * 4096u, src + r * 1024);
            } else {
                CP_ASYNC16(dst, fc_b2 + t * 4);
            }
            CP_COMMIT();
        }
    }

    // stage partials
    #pragma unroll
    for (int nl = 0; nl < 4; nl++) {
        #pragma unroll
        for (int q = 0; q < 4; q++)
            partS[(nl*16 + oq*4 + q) * 68 + g] = accS[nl][q];
        #pragma unroll
        for (int x = 0; x < 3; x++)
            #pragma unroll
            for (int q = 0; q < 4; q++)
                partV[(nl*48 + (oq*4 + q)*3 + x) * 68 + g] = accV[nl][x*4 + q];
    }
    __syncthreads();

    // --- phase 3: reduce over 64 groups, apply scale ---
    {
        float scale = INV_FAN / sm[OFF_DSUM];
        if (t < 64) {
            int nl = t >> 4, o = t & 15;
            const float4* row = (const float4*)(partS + (nl*16 + o) * 68);
            float s = 0.f;
            #pragma unroll
            for (int j = 0; j < 16; j++) {
                float4 v = row[j];
                s += (v.x + v.y) + (v.z + v.w);
            }
            outsS[nl*16 + o] = s * scale;
        } else {
            int u = t - 64;
            int nl = u / 48, j = u % 48;
            const float4* row = (const float4*)(partV + (nl*48 + j) * 68);
            float s = 0.f;
            #pragma unroll
            for (int k = 0; k < 16; k++) {
                float4 v = row[k];
                s += (v.x + v.y) + (v.z + v.w);
            }
            outvS[nl*48 + j] = s * scale;
        }
    }
    __syncthreads();

    // --- phase 4: output linear (/4) + residual ---
    {
        int nl = t >> 6, u = t & 63;
        const float* na = node_attr + (size_t)(node0 + nl) * 64;
        float r;
        if (u < 16) {
            float s = 0.f;
            #pragma unroll
            for (int o = 0; o < 16; o++) s += outsS[nl*16 + o] * wos[o * 16 + u];
            r = s * 0.25f + na[u];
        } else {
            int idx = u - 16;
            int o2 = idx / 3, x = idx % 3;
            float s = 0.f;
            #pragma unroll
            for (int o = 0; o < 16; o++) s += outvS[nl*48 + o * 3 + x] * wov[o * 16 + o2];
            r = s * 0.25f + na[u];
        }
        out[(size_t)(node0 + nl) * 64 + u] = r;
    }
}

extern "C" void kernel_launch(void* const* d_in, const int* in_sizes, int n_in,
                              void* d_out, int out_size) {
    const float* node_attr    = (const float*)d_in[0];
    const float* edge_attr    = (const float*)d_in[1];
    const float* edge_sh      = (const float*)d_in[2];
    const float* mask         = (const float*)d_in[3];
    const float* w_lin_in_s   = (const float*)d_in[4];
    const float* w_lin_in_v   = (const float*)d_in[5];
    const float* fc_w1        = (const float*)d_in[6];
    const float* fc_b1        = (const float*)d_in[7];
    const float* fc_w2        = (const float*)d_in[8];
    const float* fc_b2        = (const float*)d_in[9];
    const float* w_lin_out_s  = (const float*)d_in[10];
    const float* w_lin_out_v  = (const float*)d_in[11];
    float* out = (float*)d_out;

    static int smem_set = 0;
    if (!smem_set) {
        cudaFuncSetAttribute(node_kernel,
                             cudaFuncAttributeMaxDynamicSharedMemorySize, SMEM_BYTES);
        smem_set = 1;
    }

    edge_kernel<<<NNODE, 256>>>(edge_attr, edge_sh, mask, fc_w1, fc_b1);
    node_kernel<<<NNODE / 4, 256, SMEM_BYTES>>>(node_attr, mask,
                                    w_lin_in_s, w_lin_in_v,
                                    fc_w2, fc_b2, w_lin_out_s, w_lin_out_v, out);
}